// round 13
// baseline (speedup 1.0000x reference)
#include <cuda_runtime.h>
#include <cuda_bf16.h>
#include <cstdint>

#define BDIM 64
#define TDIM 512
#define INDIM 128
#define HDIM 512
#define G3 (3*HDIM)

// ---------------- static device scratch ----------------
__device__ float g_h[2][BDIM * HDIM];                 // ping-pong hidden state (fp32)
__device__ __align__(128) unsigned g_bar[4][32];
#define AMAX ((size_t)BDIM * TDIM * HDIM)
__device__ __nv_bfloat16 g_ahi[AMAX], g_alo[AMAX];    // layer-0 output seq (bf16 hi/lo)
__device__ __nv_bfloat16 g_xhi[(size_t)BDIM * TDIM * INDIM];  // X split
__device__ __nv_bfloat16 g_xlo[(size_t)BDIM * TDIM * INDIM];

typedef unsigned long long ull;

__device__ __forceinline__ float sigm(float x) { return 1.f / (1.f + __expf(-x)); }
__device__ __forceinline__ float tanh_fast(float x) {
    float e = __expf(2.f * x);
    return 1.f - 2.f / (e + 1.f);
}
__device__ __forceinline__ uint32_t smem_u32(const void* p) {
    uint32_t a;
    asm("{ .reg .u64 t; cvta.to.shared.u64 t, %1; cvt.u32.u64 %0, t; }" : "=r"(a) : "l"(p));
    return a;
}
__device__ __forceinline__ void cp16(uint32_t saddr, const void* g) {
    asm volatile("cp.async.cg.shared.global [%0], [%1], 16;" :: "r"(saddr), "l"(g));
}
__device__ __forceinline__ void ldsm4(uint32_t& r0, uint32_t& r1, uint32_t& r2, uint32_t& r3,
                                      uint32_t addr) {
    asm volatile("ldmatrix.sync.aligned.m8n8.x4.shared.b16 {%0,%1,%2,%3}, [%4];"
                 : "=r"(r0), "=r"(r1), "=r"(r2), "=r"(r3) : "r"(addr));
}
__device__ __forceinline__ void mma16816(float* d, const uint32_t* a, const uint32_t* b) {
    asm volatile(
        "mma.sync.aligned.m16n8k16.row.col.f32.bf16.bf16.f32 "
        "{%0,%1,%2,%3}, {%4,%5,%6,%7}, {%8,%9}, {%0,%1,%2,%3};"
        : "+f"(d[0]), "+f"(d[1]), "+f"(d[2]), "+f"(d[3])
        : "r"(a[0]), "r"(a[1]), "r"(a[2]), "r"(a[3]), "r"(b[0]), "r"(b[1]));
}

// fp32x4 -> packed bf16 hi/lo (uint2 = 4 bf16)
__device__ __forceinline__ void cvt_pair(float4 v, uint2& hi, uint2& lo) {
    __nv_bfloat162 h0 = __floats2bfloat162_rn(v.x, v.y);
    __nv_bfloat162 h1 = __floats2bfloat162_rn(v.z, v.w);
    float2 f0 = __bfloat1622float2(h0);
    float2 f1 = __bfloat1622float2(h1);
    __nv_bfloat162 l0 = __floats2bfloat162_rn(v.x - f0.x, v.y - f0.y);
    __nv_bfloat162 l1 = __floats2bfloat162_rn(v.z - f1.x, v.w - f1.y);
    hi.x = *reinterpret_cast<unsigned*>(&h0);
    hi.y = *reinterpret_cast<unsigned*>(&h1);
    lo.x = *reinterpret_cast<unsigned*>(&l0);
    lo.y = *reinterpret_cast<unsigned*>(&l1);
}

// ============================================================================
// fp32 -> bf16 hi/lo split (X only)
// ============================================================================
__global__ void cvt_split(const float* __restrict__ x, __nv_bfloat16* __restrict__ hi,
                          __nv_bfloat16* __restrict__ lo, int n)
{
    int i = blockIdx.x * blockDim.x + threadIdx.x;
    if (i < n) {
        float v = x[i];
        __nv_bfloat16 h = __float2bfloat16(v);
        hi[i] = h;
        lo[i] = __float2bfloat16(v - __bfloat162float(h));
    }
}

// ============================================================================
// Fused persistent HMMA GRU scan: recurrence AND input projection per step.
// Grid (32 k-tiles, 4 b-groups), 256 threads, 128 resident blocks.
// - W_hh fragments register-resident (R10-validated); h exchange fp32 (R10).
// - W_ih hi/lo persistent in smem; per step: acc_x += x(t) @ W_ih (x staged
//   via cp.async ISSUED BEFORE the barrier poll -> fully hidden).
// - n-gate keeps snx/snh separate (r multiplies only the h part).
// ============================================================================
#define HP 520
#define SRP2 1058                   // reduce pitch (floats) per warp

template<int KX, bool WRITE_SEQ>
__global__ void __launch_bounds__(256, 1) scan_kernel(
    const float* __restrict__ W_hh, const float* __restrict__ W_ih,
    const float* __restrict__ b_hh, const float* __restrict__ b_ih,
    const __nv_bfloat16* __restrict__ xhi, const __nv_bfloat16* __restrict__ xlo,
    float* __restrict__ h0buf, float* __restrict__ h1buf,
    __nv_bfloat16* __restrict__ seq_hi, __nv_bfloat16* __restrict__ seq_lo)
{
    constexpr int XP = (KX == 512) ? 520 : 136;     // x/W_ih smem pitch (bf16)
    constexpr int XK16 = KX / 128;                  // x k16 steps per warp
    constexpr uint32_t WIH_LO_B = 48 * XP * 2;      // lo tile offset in region A
    constexpr uint32_t BB = 2 * WIH_LO_B;           // region B base
    constexpr uint32_t WHH_LO_B = 48 * HP * 2;      // Whh staging lo (in region B)
    constexpr uint32_t H_HI = BB;
    constexpr uint32_t H_LO = BB + 16 * HP * 2;     // 16640
    constexpr uint32_t X_HI = BB + 2 * 16 * HP * 2; // 33280
    constexpr uint32_t XT  = 16 * XP * 2;
    constexpr uint32_t X_LO = X_HI + XT;
    constexpr uint32_t R_OFF = X_HI + 2 * XT;

    extern __shared__ char sms[];
    const uint32_t sb = smem_u32(sms);
    float* sR = (float*)(sms + R_OFF);

    const int tid = threadIdx.x;
    const int wid = tid >> 5;
    const int lane = tid & 31;
    const int k0 = blockIdx.x * 16;
    const int b0 = blockIdx.y * 16;

    // ---- preload W_ih hi/lo into persistent smem region A ----
    for (int i = tid; i < 48 * (KX / 4); i += 256) {
        int r = i / (KX / 4), c4 = i % (KX / 4);
        int g = r >> 4, kr = r & 15;
        float4 v = *(const float4*)&W_ih[(size_t)(g * HDIM + k0 + kr) * KX + c4 * 4];
        uint2 hi, lo; cvt_pair(v, hi, lo);
        *(uint2*)(sms + (r * XP + c4 * 4) * 2) = hi;
        *(uint2*)(sms + WIH_LO_B + (r * XP + c4 * 4) * 2) = lo;
    }

    // ---- stage W_hh hi/lo into region B (temporary) ----
    for (int i = tid; i < 48 * 128; i += 256) {
        int r = i >> 7, c4 = i & 127;
        int g = r >> 4, kr = r & 15;
        float4 v = *(const float4*)&W_hh[(size_t)(g * HDIM + k0 + kr) * HDIM + c4 * 4];
        uint2 hi, lo; cvt_pair(v, hi, lo);
        *(uint2*)(sms + BB + (r * HP + c4 * 4) * 2) = hi;
        *(uint2*)(sms + BB + WHH_LO_B + (r * HP + c4 * 4) * 2) = lo;
    }
    __syncthreads();

    // ---- preload W_hh fragments into registers (one time) ----
    const int jb = wid * 64;              // warp K-slice base in h (K=512)
    uint32_t WH[4][3][4], WL[4][3][4];
    #pragma unroll
    for (int k16 = 0; k16 < 4; k16++)
        #pragma unroll
        for (int ng = 0; ng < 3; ng++) {
            uint32_t addr = sb + BB
                + (uint32_t)((ng * 16 + (lane >> 4) * 8 + (lane & 7)) * HP
                             + jb + k16 * 16 + ((lane >> 3) & 1) * 8) * 2;
            ldsm4(WH[k16][ng][0], WH[k16][ng][1], WH[k16][ng][2], WH[k16][ng][3], addr);
            ldsm4(WL[k16][ng][0], WL[k16][ng][1], WL[k16][ng][2], WL[k16][ng][3],
                  addr + WHH_LO_B);
        }
    __syncthreads();   // region B recycled: h staging + x staging + reduce

    // ---- ldsm bases ----
    const uint32_t aHi = sb + H_HI
        + (uint32_t)((lane & 15) * HP + jb + (lane >> 4) * 8) * 2;
    const uint32_t aLo = aHi + (H_LO - H_HI);
    const int xjb = wid * (KX / 8);       // warp K-slice base in x
    const uint32_t axHi = sb + X_HI
        + (uint32_t)((lane & 15) * XP + xjb + (lane >> 4) * 8) * 2;
    const uint32_t axLo = axHi + XT;
    // W_ih fragment base (per k16/ng added in loop)
    const uint32_t wxBase = sb
        + (uint32_t)(((lane >> 4) * 8 + (lane & 7)) * XP + xjb + ((lane >> 3) & 1) * 8) * 2;

    // ---- per-thread epilogue cell ----
    const int m = tid >> 4;
    const int kq = tid & 15;
    const int bgl = b0 + m;
    const int kg = k0 + kq;
    const float bhr = b_hh[kg],            bir = b_ih[kg];
    const float bhz = b_hh[HDIM + kg],     biz = b_ih[HDIM + kg];
    const float bhn = b_hh[2*HDIM + kg],   bin = b_ih[2*HDIM + kg];
    const size_t cellIdx = (size_t)bgl * HDIM + kg;

    unsigned* bar = &g_bar[blockIdx.y][0];
    float hold = 0.f;

    for (int t = 0; t < TDIM; t++) {
        const float* hprev = (t & 1) ? h1buf : h0buf;
        float* hnext = (t & 1) ? h0buf : h1buf;

        // ---- stage x(t) via cp.async BEFORE the barrier (static data) ----
        {
            constexpr int NCH = 2 * 16 * (KX / 8);   // 16B chunks (hi+lo)
            #pragma unroll
            for (int i = tid; i < NCH; i += 256) {
                const int tile = i >= NCH / 2;
                const int j = tile ? (i - NCH / 2) : i;
                const int r = j / (KX / 8);
                const int c8 = j % (KX / 8);
                const __nv_bfloat16* src = (tile ? xlo : xhi)
                    + ((size_t)(b0 + r) * TDIM + t) * KX + c8 * 8;
                cp16(sb + (tile ? X_LO : X_HI) + (uint32_t)(r * XP + c8 * 8) * 2, src);
            }
            asm volatile("cp.async.commit_group;");
        }

        // ---- barrier: h(t) available when bar >= 32*t ----
        if (tid == 0) {
            const unsigned target = 32u * (unsigned)t;
            unsigned vv;
            do {
                asm volatile("ld.acquire.gpu.global.u32 %0, [%1];"
                             : "=r"(vv) : "l"(bar) : "memory");
            } while (vv < target);
        }
        __syncthreads();

        // ---- stage h tile: 16 rows x 512, fp32 -> bf16 hi/lo (coalesced) ----
        #pragma unroll
        for (int i = tid; i < 16 * 128; i += 256) {
            int r = i >> 7, c4 = i & 127;
            float4 v = __ldcg((const float4*)&hprev[(size_t)(b0 + r) * HDIM + c4 * 4]);
            uint2 hi, lo; cvt_pair(v, hi, lo);
            *(uint2*)(sms + H_HI + (r * HP + c4 * 4) * 2) = hi;
            *(uint2*)(sms + H_LO + (r * HP + c4 * 4) * 2) = lo;
        }
        asm volatile("cp.async.wait_group 0;");
        __syncthreads();

        // ---- MMA: h-side (W from regs) + x-side (W_ih from smem) ----
        float acc_h[6][4], acc_x[6][4];
        #pragma unroll
        for (int nt = 0; nt < 6; nt++)
            #pragma unroll
            for (int q = 0; q < 4; q++) { acc_h[nt][q] = 0.f; acc_x[nt][q] = 0.f; }

        #pragma unroll
        for (int k16 = 0; k16 < 4; k16++) {
            const uint32_t ko = k16 * 32;
            uint32_t Ah[4], Al[4];
            ldsm4(Ah[0], Ah[1], Ah[2], Ah[3], aHi + ko);
            ldsm4(Al[0], Al[1], Al[2], Al[3], aLo + ko);
            #pragma unroll
            for (int ng = 0; ng < 3; ng++)
                #pragma unroll
                for (int s = 0; s < 2; s++) {
                    float* d = acc_h[2 * ng + s];
                    mma16816(d, Ah, &WH[k16][ng][s * 2]);
                    mma16816(d, Ah, &WL[k16][ng][s * 2]);
                    mma16816(d, Al, &WH[k16][ng][s * 2]);
                }
        }
        #pragma unroll
        for (int k16 = 0; k16 < XK16; k16++) {
            const uint32_t ko = k16 * 32;
            uint32_t Ah[4], Al[4];
            ldsm4(Ah[0], Ah[1], Ah[2], Ah[3], axHi + ko);
            ldsm4(Al[0], Al[1], Al[2], Al[3], axLo + ko);
            #pragma unroll
            for (int ng = 0; ng < 3; ng++) {
                const uint32_t wa = wxBase + (uint32_t)(ng * 16 * XP + k16 * 16) * 2;
                uint32_t Bh[4], Bl[4];
                ldsm4(Bh[0], Bh[1], Bh[2], Bh[3], wa);
                ldsm4(Bl[0], Bl[1], Bl[2], Bl[3], wa + WIH_LO_B);
                #pragma unroll
                for (int s = 0; s < 2; s++) {
                    float* d = acc_x[2 * ng + s];
                    mma16816(d, Ah, &Bh[s * 2]);
                    mma16816(d, Ah, &Bl[s * 2]);
                    mma16816(d, Al, &Bh[s * 2]);
                }
            }
        }

        // ---- dump partials: r,z merged; n-gate split (h vs x) ----
        {
            float* outp = sR + wid * SRP2 + (lane >> 2) * 66 + (lane & 3) * 2;
            #pragma unroll
            for (int nt = 0; nt < 4; nt++) {   // r,z merged (cols 0..31)
                *(float2*)&outp[nt * 8] =
                    make_float2(acc_h[nt][0] + acc_x[nt][0], acc_h[nt][1] + acc_x[nt][1]);
                *(float2*)&outp[8 * 66 + nt * 8] =
                    make_float2(acc_h[nt][2] + acc_x[nt][2], acc_h[nt][3] + acc_x[nt][3]);
            }
            #pragma unroll
            for (int j = 0; j < 2; j++) {      // nh (cols 32..47)
                *(float2*)&outp[32 + j * 8] = make_float2(acc_h[4+j][0], acc_h[4+j][1]);
                *(float2*)&outp[8 * 66 + 32 + j * 8] = make_float2(acc_h[4+j][2], acc_h[4+j][3]);
            }
            #pragma unroll
            for (int j = 0; j < 2; j++) {      // nx (cols 48..63)
                *(float2*)&outp[48 + j * 8] = make_float2(acc_x[4+j][0], acc_x[4+j][1]);
                *(float2*)&outp[8 * 66 + 48 + j * 8] = make_float2(acc_x[4+j][2], acc_x[4+j][3]);
            }
        }
        __syncthreads();

        // ---- cross-warp reduce + gates ----
        float sr = 0.f, sz = 0.f, snh = 0.f, snx = 0.f;
        #pragma unroll
        for (int w = 0; w < 8; w++) {
            const float* rr = sR + w * SRP2 + m * 66;
            sr  += rr[kq];
            sz  += rr[16 + kq];
            snh += rr[32 + kq];
            snx += rr[48 + kq];
        }

        float r = sigm(sr + bir + bhr);
        float z = sigm(sz + biz + bhz);
        float n = tanh_fast(snx + bin + r * (snh + bhn));
        float hnew = (1.f - z) * n + z * hold;
        hold = hnew;

        __stcg(&hnext[cellIdx], hnew);

        __syncthreads();
        if (tid == 0)
            asm volatile("red.release.gpu.global.add.u32 [%0], %1;"
                         :: "l"(bar), "r"(1u) : "memory");

        // off-critical-path: layer-0 sequence output (bf16 hi/lo)
        if (WRITE_SEQ) {
            __nv_bfloat16 hb = __float2bfloat16(hnew);
            __nv_bfloat16 lb = __float2bfloat16(hnew - __bfloat162float(hb));
            const size_t idx = ((size_t)bgl * TDIM + t) * HDIM + kg;
            seq_hi[idx] = hb;
            seq_lo[idx] = lb;
        }
    }
}

// host-side smem sizes (mirror of kernel constexprs)
static constexpr int smem_scan(int XPv) {
    int XT = 16 * XPv * 2;
    int Bneed = 2 * 16 * 520 * 2 + 2 * XT + 8 * SRP2 * 4;   // h + x + reduce
    int Bpre = 2 * 48 * 520 * 2;                            // Whh staging
    int B = Bneed > Bpre ? Bneed : Bpre;
    return 2 * 48 * XPv * 2 + B;
}

// ---------------------------------------------------------------------------
__global__ void init_kernel(float* h) {
    int i = blockIdx.x * blockDim.x + threadIdx.x;
    h[i] = 0.f;                       // zeros both ping-pong buffers (2*64*512)
    if (i < 128) ((unsigned*)g_bar)[i] = 0u;
}

__global__ void fc_kernel(const float* __restrict__ h, const float* __restrict__ W,
                          const float* __restrict__ bias, float* __restrict__ out)
{
    const int b = blockIdx.x;
    float s = 0.f;
    for (int k = threadIdx.x; k < HDIM; k += 128)
        s += h[(size_t)b * HDIM + k] * W[k];
    __shared__ float red[128];
    red[threadIdx.x] = s; __syncthreads();
    for (int off = 64; off > 0; off >>= 1) {
        if (threadIdx.x < off) red[threadIdx.x] += red[threadIdx.x + off];
        __syncthreads();
    }
    if (threadIdx.x == 0) out[b] = red[0] + bias[0];
}

// ---------------------------------------------------------------------------
extern "C" void kernel_launch(void* const* d_in, const int* in_sizes, int n_in,
                              void* d_out, int out_size)
{
    const float* X     = (const float*)d_in[0];
    const float* W_ih0 = (const float*)d_in[1];
    const float* W_hh0 = (const float*)d_in[2];
    const float* b_ih0 = (const float*)d_in[3];
    const float* b_hh0 = (const float*)d_in[4];
    const float* W_ih1 = (const float*)d_in[5];
    const float* W_hh1 = (const float*)d_in[6];
    const float* b_ih1 = (const float*)d_in[7];
    const float* b_hh1 = (const float*)d_in[8];
    const float* fc_W  = (const float*)d_in[9];
    const float* fc_b  = (const float*)d_in[10];
    float* out = (float*)d_out;

    float *hbuf;
    __nv_bfloat16 *ahi, *alo, *xhi, *xlo;
    cudaGetSymbolAddress((void**)&hbuf, g_h);
    cudaGetSymbolAddress((void**)&ahi, g_ahi);
    cudaGetSymbolAddress((void**)&alo, g_alo);
    cudaGetSymbolAddress((void**)&xhi, g_xhi);
    cudaGetSymbolAddress((void**)&xlo, g_xlo);

    const int S0 = smem_scan(136);   // layer-0
    const int S1 = smem_scan(520);   // layer-1
    cudaFuncSetAttribute(scan_kernel<INDIM, true>,
                         cudaFuncAttributeMaxDynamicSharedMemorySize, S0);
    cudaFuncSetAttribute(scan_kernel<HDIM, false>,
                         cudaFuncAttributeMaxDynamicSharedMemorySize, S1);

    const size_t HB = (size_t)BDIM * HDIM;
    const int M = BDIM * TDIM;                 // 32768

    // ---- Layer 0 (fused projection + scan) ----
    cvt_split<<<(M * INDIM + 255) / 256, 256>>>(X, xhi, xlo, M * INDIM);
    init_kernel<<<128, 512>>>(hbuf);
    scan_kernel<INDIM, true><<<dim3(32, 4), 256, S0>>>(
        W_hh0, W_ih0, b_hh0, b_ih0, xhi, xlo, hbuf, hbuf + HB, ahi, alo);

    // ---- Layer 1 (fused; x = layer-0 seq, already bf16 hi/lo) ----
    init_kernel<<<128, 512>>>(hbuf);
    scan_kernel<HDIM, false><<<dim3(32, 4), 256, S1>>>(
        W_hh1, W_ih1, b_hh1, b_ih1, ahi, alo, hbuf, hbuf + HB, nullptr, nullptr);

    // final h after 512 steps sits in parity-0 buffer
    fc_kernel<<<BDIM, 128>>>(hbuf, fc_W, fc_b, out);
}

// round 14
// speedup vs baseline: 1.0870x; 1.0870x over previous
#include <cuda_runtime.h>
#include <cuda_bf16.h>
#include <cstdint>

#define BDIM 64
#define TDIM 512
#define INDIM 128
#define HDIM 512
#define G3 (3*HDIM)

// ---------------- static device scratch ----------------
__device__ float g_xg[(size_t)BDIM * TDIM * G3];
__device__ float g_h[2][BDIM * HDIM];
__device__ __align__(128) unsigned g_bar[4][32];
#define AMAX ((size_t)BDIM * TDIM * HDIM)
__device__ __nv_bfloat16 g_ahi[AMAX], g_alo[AMAX];
__device__ __nv_bfloat16 g_whi[G3 * HDIM], g_wlo[G3 * HDIM];

typedef unsigned long long ull;

__device__ __forceinline__ float sigm(float x) { return 1.f / (1.f + __expf(-x)); }
__device__ __forceinline__ float tanh_fast(float x) {
    float e = __expf(2.f * x);
    return 1.f - 2.f / (e + 1.f);
}
__device__ __forceinline__ uint32_t smem_u32(const void* p) {
    uint32_t a;
    asm("{ .reg .u64 t; cvta.to.shared.u64 t, %1; cvt.u32.u64 %0, t; }" : "=r"(a) : "l"(p));
    return a;
}
__device__ __forceinline__ void cp16(uint32_t saddr, const void* g) {
    asm volatile("cp.async.cg.shared.global [%0], [%1], 16;" :: "r"(saddr), "l"(g));
}
__device__ __forceinline__ void ldsm4(uint32_t& r0, uint32_t& r1, uint32_t& r2, uint32_t& r3,
                                      uint32_t addr) {
    asm volatile("ldmatrix.sync.aligned.m8n8.x4.shared.b16 {%0,%1,%2,%3}, [%4];"
                 : "=r"(r0), "=r"(r1), "=r"(r2), "=r"(r3) : "r"(addr));
}
__device__ __forceinline__ void mma16816(float* d, const uint32_t* a, const uint32_t* b) {
    asm volatile(
        "mma.sync.aligned.m16n8k16.row.col.f32.bf16.bf16.f32 "
        "{%0,%1,%2,%3}, {%4,%5,%6,%7}, {%8,%9}, {%0,%1,%2,%3};"
        : "+f"(d[0]), "+f"(d[1]), "+f"(d[2]), "+f"(d[3])
        : "r"(a[0]), "r"(a[1]), "r"(a[2]), "r"(a[3]), "r"(b[0]), "r"(b[1]));
}

// fp32x4 -> packed bf16 hi/lo (uint2 = 4 bf16)
__device__ __forceinline__ void cvt_pair(float4 v, uint2& hi, uint2& lo) {
    __nv_bfloat162 h0 = __floats2bfloat162_rn(v.x, v.y);
    __nv_bfloat162 h1 = __floats2bfloat162_rn(v.z, v.w);
    float2 f0 = __bfloat1622float2(h0);
    float2 f1 = __bfloat1622float2(h1);
    __nv_bfloat162 l0 = __floats2bfloat162_rn(v.x - f0.x, v.y - f0.y);
    __nv_bfloat162 l1 = __floats2bfloat162_rn(v.z - f1.x, v.w - f1.y);
    hi.x = *reinterpret_cast<unsigned*>(&h0);
    hi.y = *reinterpret_cast<unsigned*>(&h1);
    lo.x = *reinterpret_cast<unsigned*>(&l0);
    lo.y = *reinterpret_cast<unsigned*>(&l1);
}

// ============================================================================
// fp32 -> bf16 hi/lo split (for projection GEMM operands)
// ============================================================================
__global__ void cvt_split(const float* __restrict__ x, __nv_bfloat16* __restrict__ hi,
                          __nv_bfloat16* __restrict__ lo, int n)
{
    int i = blockIdx.x * blockDim.x + threadIdx.x;
    if (i < n) {
        float v = x[i];
        __nv_bfloat16 h = __float2bfloat16(v);
        hi[i] = h;
        lo[i] = __float2bfloat16(v - __bfloat162float(h));
    }
}

// ============================================================================
// HMMA bf16 split-precision projection GEMM (R7-passing, unchanged)
// ============================================================================
#define GP 40
#define GTILE_B (128*GP*2)
#define GBUF_B (4*GTILE_B)
#define SMEM_GEMM (2*GBUF_B)

template<int K>
__global__ void __launch_bounds__(256) gemm_kernel(
    const __nv_bfloat16* __restrict__ Ahi, const __nv_bfloat16* __restrict__ Alo,
    const __nv_bfloat16* __restrict__ Whi, const __nv_bfloat16* __restrict__ Wlo,
    const float* __restrict__ bias, float* __restrict__ C)
{
    extern __shared__ __nv_bfloat16 smg[];
    const uint32_t sbase = smem_u32(smg);
    const int tid = threadIdx.x;
    const int wid = tid >> 5;
    const int lane = tid & 31;
    const int m0 = blockIdx.x * 128;
    const int n0 = blockIdx.y * 128;
    constexpr int NC = K / 32;

    const __nv_bfloat16* srcs[4] = { Ahi + (size_t)m0 * K, Alo + (size_t)m0 * K,
                                     Whi + (size_t)n0 * K, Wlo + (size_t)n0 * K };

    const int wm = (wid & 1) * 64;
    const int wn = (wid >> 1) * 32;
    const uint32_t aOff = (uint32_t)((wm + (lane & 15)) * GP + (lane >> 4) * 8) * 2;
    const uint32_t bOff = (uint32_t)((wn + (lane >> 4) * 8 + (lane & 7)) * GP
                                     + ((lane >> 3) & 1) * 8) * 2;

    float acc[4][4][4];
    #pragma unroll
    for (int mt = 0; mt < 4; mt++)
        #pragma unroll
        for (int nt = 0; nt < 4; nt++)
            #pragma unroll
            for (int q = 0; q < 4; q++) acc[mt][nt][q] = 0.f;

    auto stage = [&](int c, int p) {
        const uint32_t db = sbase + p * GBUF_B;
        #pragma unroll
        for (int t4 = 0; t4 < 4; t4++) {
            const __nv_bfloat16* s = srcs[t4] + c * 32;
            const uint32_t tb = db + t4 * GTILE_B;
            #pragma unroll
            for (int i = tid; i < 512; i += 256) {
                int r = i >> 2, ch = i & 3;
                cp16(tb + (uint32_t)(r * GP + ch * 8) * 2, s + (size_t)r * K + ch * 8);
            }
        }
        asm volatile("cp.async.commit_group;");
    };

    stage(0, 0);
    for (int c = 0; c < NC; c++) {
        const int p = c & 1;
        if (c + 1 < NC) {
            stage(c + 1, p ^ 1);
            asm volatile("cp.async.wait_group 1;");
        } else {
            asm volatile("cp.async.wait_group 0;");
        }
        __syncthreads();

        const uint32_t ab = sbase + p * GBUF_B + aOff;
        const uint32_t bb = sbase + p * GBUF_B + 2 * GTILE_B + bOff;

        #pragma unroll
        for (int k16 = 0; k16 < 2; k16++) {
            uint32_t Ah[4][4], Al[4][4], Bh[2][4], Bl[2][4];
            #pragma unroll
            for (int mt = 0; mt < 4; mt++) {
                const uint32_t a = ab + (uint32_t)(mt * 16 * GP + k16 * 16) * 2;
                ldsm4(Ah[mt][0], Ah[mt][1], Ah[mt][2], Ah[mt][3], a);
                ldsm4(Al[mt][0], Al[mt][1], Al[mt][2], Al[mt][3], a + GTILE_B);
            }
            #pragma unroll
            for (int np = 0; np < 2; np++) {
                const uint32_t b = bb + (uint32_t)(np * 16 * GP + k16 * 16) * 2;
                ldsm4(Bh[np][0], Bh[np][1], Bh[np][2], Bh[np][3], b);
                ldsm4(Bl[np][0], Bl[np][1], Bl[np][2], Bl[np][3], b + GTILE_B);
            }
            #pragma unroll
            for (int mt = 0; mt < 4; mt++)
                #pragma unroll
                for (int nt = 0; nt < 4; nt++) {
                    const uint32_t* bh = &Bh[nt >> 1][(nt & 1) * 2];
                    const uint32_t* bl = &Bl[nt >> 1][(nt & 1) * 2];
                    mma16816(acc[mt][nt], Ah[mt], bh);
                    mma16816(acc[mt][nt], Ah[mt], bl);
                    mma16816(acc[mt][nt], Al[mt], bh);
                }
        }
        __syncthreads();
    }

    const int mrow = m0 + wm + (lane >> 2);
    const int ncol = n0 + wn + (lane & 3) * 2;
    #pragma unroll
    for (int nt = 0; nt < 4; nt++) {
        const int n = ncol + nt * 8;
        const float b0 = __ldg(bias + n);
        const float b1 = __ldg(bias + n + 1);
        #pragma unroll
        for (int mt = 0; mt < 4; mt++) {
            const int m = mrow + mt * 16;
            float2 o0 = make_float2(acc[mt][nt][0] + b0, acc[mt][nt][1] + b1);
            float2 o1 = make_float2(acc[mt][nt][2] + b0, acc[mt][nt][3] + b1);
            *(float2*)&C[(size_t)m * G3 + n] = o0;
            *(float2*)&C[(size_t)(m + 8) * G3 + n] = o1;
        }
    }
}

// ============================================================================
// Persistent HMMA GRU scan (R10 structure + 3 validated micro-fixes):
// - W_hh fragments register-resident; coalesced fp32 h exchange (R10).
// - hold carried in a register (cell self-consumption).
// - xg prefetch issued BEFORE the barrier poll.
// - WRITE_SEQ stores moved AFTER the release.
// ============================================================================
#define HP 520
#define OFF_WLO 49920              // 48*520*2
#define SMEM_SCAN (2*49920)        // 99840 B
// reuse after W preload:
#define OFF_HHI 0
#define OFF_HLO 16640              // 16*520*2
#define OFF_R   33280
#define SRP 800                    // reduce pitch (floats) per warp

template<bool WRITE_SEQ>
__global__ void __launch_bounds__(256, 1) scan_kernel(
    const float* __restrict__ W_hh, const float* __restrict__ b_hh,
    const float* __restrict__ xg, float* __restrict__ h0buf,
    float* __restrict__ h1buf,
    __nv_bfloat16* __restrict__ seq_hi, __nv_bfloat16* __restrict__ seq_lo)
{
    extern __shared__ char sms[];
    const uint32_t sb = smem_u32(sms);
    float* sR = (float*)(sms + OFF_R);

    const int tid = threadIdx.x;
    const int wid = tid >> 5;
    const int lane = tid & 31;
    const int k0 = blockIdx.x * 16;
    const int b0 = blockIdx.y * 16;

    // ---- stage W_hh hi/lo into smem (one time) ----
    for (int i = tid; i < 48 * 128; i += 256) {
        int r = i >> 7, c4 = i & 127;
        int g = r >> 4, kr = r & 15;
        float4 v = *(const float4*)&W_hh[(size_t)(g * HDIM + k0 + kr) * HDIM + c4 * 4];
        uint2 hi, lo; cvt_pair(v, hi, lo);
        *(uint2*)(sms + (r * HP + c4 * 4) * 2) = hi;
        *(uint2*)(sms + OFF_WLO + (r * HP + c4 * 4) * 2) = lo;
    }
    __syncthreads();

    // ---- preload W fragments into registers (one time) ----
    const int jb = wid * 64;   // this warp's K-slice base
    uint32_t WH[4][3][4], WL[4][3][4];
    #pragma unroll
    for (int k16 = 0; k16 < 4; k16++)
        #pragma unroll
        for (int ng = 0; ng < 3; ng++) {
            uint32_t addr = sb + (uint32_t)((ng * 16 + (lane >> 4) * 8 + (lane & 7)) * HP
                                            + jb + k16 * 16 + ((lane >> 3) & 1) * 8) * 2;
            ldsm4(WH[k16][ng][0], WH[k16][ng][1], WH[k16][ng][2], WH[k16][ng][3], addr);
            ldsm4(WL[k16][ng][0], WL[k16][ng][1], WL[k16][ng][2], WL[k16][ng][3],
                  addr + OFF_WLO);
        }
    __syncthreads();   // smem region now recycled for h staging + reduce

    // ---- A-side ldsm base (canonical layout) ----
    const uint32_t aHi = sb + OFF_HHI
        + (uint32_t)((lane & 15) * HP + jb + (lane >> 4) * 8) * 2;
    const uint32_t aLo = aHi + (OFF_HLO - OFF_HHI);

    // ---- per-thread epilogue cell ----
    const int m = tid >> 4;
    const int kq = tid & 15;
    const int bgl = b0 + m;
    const int kg = k0 + kq;
    const float bhr = b_hh[kg];
    const float bhz = b_hh[HDIM + kg];
    const float bhn = b_hh[2 * HDIM + kg];
    const float* xgb = xg + (size_t)bgl * TDIM * G3 + kg;
    const size_t cellIdx = (size_t)bgl * HDIM + kg;

    unsigned* bar = &g_bar[blockIdx.y][0];
    float hold = 0.f;   // h(0)=0; thereafter this thread's own previous output

    for (int t = 0; t < TDIM; t++) {
        const float* hprev = (t & 1) ? h1buf : h0buf;
        float* hnext = (t & 1) ? h0buf : h1buf;

        // prefetch input gates BEFORE the poll (static data, overlaps barrier)
        const float* xt = xgb + (size_t)t * G3;
        float xr = __ldcg(xt);
        float xz = __ldcg(xt + HDIM);
        float xn = __ldcg(xt + 2 * HDIM);

        if (tid == 0) {
            const unsigned target = 32u * (unsigned)t;
            unsigned vv;
            do {
                asm volatile("ld.acquire.gpu.global.u32 %0, [%1];"
                             : "=r"(vv) : "l"(bar) : "memory");
            } while (vv < target);
        }
        __syncthreads();

        // stage h tile: 16 rows x 512, fp32 -> bf16 hi/lo (coalesced)
        #pragma unroll
        for (int i = tid; i < 16 * 128; i += 256) {
            int r = i >> 7, c4 = i & 127;
            float4 v = __ldcg((const float4*)&hprev[(size_t)(b0 + r) * HDIM + c4 * 4]);
            uint2 hi, lo; cvt_pair(v, hi, lo);
            *(uint2*)(sms + OFF_HHI + (r * HP + c4 * 4) * 2) = hi;
            *(uint2*)(sms + OFF_HLO + (r * HP + c4 * 4) * 2) = lo;
        }
        __syncthreads();

        // ---- MMA: warp's K-slice of 64 (A from smem ldsm, W from regs) ----
        float acc[6][4];
        #pragma unroll
        for (int nt = 0; nt < 6; nt++)
            #pragma unroll
            for (int q = 0; q < 4; q++) acc[nt][q] = 0.f;

        #pragma unroll
        for (int k16 = 0; k16 < 4; k16++) {
            const uint32_t ko = k16 * 32;
            uint32_t Ah[4], Al[4];
            ldsm4(Ah[0], Ah[1], Ah[2], Ah[3], aHi + ko);
            ldsm4(Al[0], Al[1], Al[2], Al[3], aLo + ko);
            #pragma unroll
            for (int ng = 0; ng < 3; ng++)
                #pragma unroll
                for (int s = 0; s < 2; s++) {
                    float* d = acc[2 * ng + s];
                    mma16816(d, Ah, &WH[k16][ng][s * 2]);
                    mma16816(d, Ah, &WL[k16][ng][s * 2]);
                    mma16816(d, Al, &WH[k16][ng][s * 2]);
                }
        }

        // ---- dump partials: sR[wid][mrow*50 + n] ----
        {
            float* outp = sR + wid * SRP + (lane >> 2) * 50 + (lane & 3) * 2;
            #pragma unroll
            for (int nt = 0; nt < 6; nt++) {
                *(float2*)&outp[nt * 8] = make_float2(acc[nt][0], acc[nt][1]);
                *(float2*)&outp[400 + nt * 8] = make_float2(acc[nt][2], acc[nt][3]);
            }
        }
        __syncthreads();

        // ---- cross-warp reduce + gates ----
        float sr = 0.f, sz = 0.f, sn = 0.f;
        #pragma unroll
        for (int w = 0; w < 8; w++) {
            const float* rr = sR + w * SRP + m * 50;
            sr += rr[kq];
            sz += rr[16 + kq];
            sn += rr[32 + kq];
        }

        float r = sigm(xr + sr + bhr);
        float z = sigm(xz + sz + bhz);
        float n = tanh_fast(xn + r * (sn + bhn));
        float hnew = (1.f - z) * n + z * hold;
        hold = hnew;

        __stcg(&hnext[cellIdx], hnew);

        __syncthreads();
        if (tid == 0)
            asm volatile("red.release.gpu.global.add.u32 [%0], %1;"
                         :: "l"(bar), "r"(1u) : "memory");

        // off-critical-path: layer-0 sequence output (bf16 hi/lo), after release
        if (WRITE_SEQ) {
            __nv_bfloat16 hh = __float2bfloat16(hnew);
            __nv_bfloat16 hl = __float2bfloat16(hnew - __bfloat162float(hh));
            const size_t idx = ((size_t)bgl * TDIM + t) * HDIM + kg;
            seq_hi[idx] = hh;
            seq_lo[idx] = hl;
        }
    }
}

// ---------------------------------------------------------------------------
__global__ void init_kernel(float* h) {
    int i = blockIdx.x * blockDim.x + threadIdx.x;
    h[i] = 0.f;
    if (i < 128) ((unsigned*)g_bar)[i] = 0u;
}

__global__ void fc_kernel(const float* __restrict__ h, const float* __restrict__ W,
                          const float* __restrict__ bias, float* __restrict__ out)
{
    const int b = blockIdx.x;
    float s = 0.f;
    for (int k = threadIdx.x; k < HDIM; k += 128)
        s += h[(size_t)b * HDIM + k] * W[k];
    __shared__ float red[128];
    red[threadIdx.x] = s; __syncthreads();
    for (int off = 64; off > 0; off >>= 1) {
        if (threadIdx.x < off) red[threadIdx.x] += red[threadIdx.x + off];
        __syncthreads();
    }
    if (threadIdx.x == 0) out[b] = red[0] + bias[0];
}

// ---------------------------------------------------------------------------
extern "C" void kernel_launch(void* const* d_in, const int* in_sizes, int n_in,
                              void* d_out, int out_size)
{
    const float* X     = (const float*)d_in[0];
    const float* W_ih0 = (const float*)d_in[1];
    const float* W_hh0 = (const float*)d_in[2];
    const float* b_ih0 = (const float*)d_in[3];
    const float* b_hh0 = (const float*)d_in[4];
    const float* W_ih1 = (const float*)d_in[5];
    const float* W_hh1 = (const float*)d_in[6];
    const float* b_ih1 = (const float*)d_in[7];
    const float* b_hh1 = (const float*)d_in[8];
    const float* fc_W  = (const float*)d_in[9];
    const float* fc_b  = (const float*)d_in[10];
    float* out = (float*)d_out;

    float *xg, *hbuf;
    __nv_bfloat16 *ahi, *alo, *whi, *wlo;
    cudaGetSymbolAddress((void**)&xg, g_xg);
    cudaGetSymbolAddress((void**)&hbuf, g_h);
    cudaGetSymbolAddress((void**)&ahi, g_ahi);
    cudaGetSymbolAddress((void**)&alo, g_alo);
    cudaGetSymbolAddress((void**)&whi, g_whi);
    cudaGetSymbolAddress((void**)&wlo, g_wlo);

    cudaFuncSetAttribute(scan_kernel<true>,
                         cudaFuncAttributeMaxDynamicSharedMemorySize, SMEM_SCAN);
    cudaFuncSetAttribute(scan_kernel<false>,
                         cudaFuncAttributeMaxDynamicSharedMemorySize, SMEM_SCAN);
    cudaFuncSetAttribute(gemm_kernel<INDIM>,
                         cudaFuncAttributeMaxDynamicSharedMemorySize, SMEM_GEMM);
    cudaFuncSetAttribute(gemm_kernel<HDIM>,
                         cudaFuncAttributeMaxDynamicSharedMemorySize, SMEM_GEMM);

    const size_t HB = (size_t)BDIM * HDIM;
    const int M = BDIM * TDIM;                 // 32768
    const dim3 ggrid(M / 128, G3 / 128);       // (256, 12)

    // ---- Layer 0 ----
    cvt_split<<<(M * INDIM + 255) / 256, 256>>>(X, ahi, alo, M * INDIM);
    cvt_split<<<(G3 * INDIM + 255) / 256, 256>>>(W_ih0, whi, wlo, G3 * INDIM);
    gemm_kernel<INDIM><<<ggrid, 256, SMEM_GEMM>>>(ahi, alo, whi, wlo, b_ih0, xg);
    init_kernel<<<128, 512>>>(hbuf);
    // scan writes h_seq directly as bf16 hi/lo into ahi/alo (layer-1 GEMM A operand)
    scan_kernel<true><<<dim3(32, 4), 256, SMEM_SCAN>>>(
        W_hh0, b_hh0, xg, hbuf, hbuf + HB, ahi, alo);

    // ---- Layer 1 ----
    cvt_split<<<(G3 * HDIM + 255) / 256, 256>>>(W_ih1, whi, wlo, G3 * HDIM);
    gemm_kernel<HDIM><<<ggrid, 256, SMEM_GEMM>>>(ahi, alo, whi, wlo, b_ih1, xg);
    init_kernel<<<128, 512>>>(hbuf);
    scan_kernel<false><<<dim3(32, 4), 256, SMEM_SCAN>>>(
        W_hh1, b_hh1, xg, hbuf, hbuf + HB, nullptr, nullptr);

    // final h (after 512 steps) sits in parity-0 buffer
    fc_kernel<<<BDIM, 128>>>(hbuf, fc_W, fc_b, out);
}